// round 1
// baseline (speedup 1.0000x reference)
#include <cuda_runtime.h>

// Problem constants
#define NB    16
#define NDIM  128
#define NPTS  16384
#define NJ    16
#define NK    128
#define NL    128
#define NR    8

typedef unsigned long long ull;

// Scratch (device globals — no allocation allowed)
__device__ float g_xhat[NB * NDIM * NL];          // [b*128+i][l]        1 MB
__device__ float g_Ht[NJ * NL * NK];              // [(j*128+l)][k]      1 MB
__device__ float g_Wt[NJ * NDIM * NDIM];          // [(j*128+o)][i]      1 MB
__device__ float g_z[NB * NDIM * NJ * NL];        // [b][o][j][l]       16 MB
__device__ float g_y[NB * NDIM * NK];             // [b*128+o][k]        1 MB

// ---------------- packed fp32x2 helpers (sm_100+ FFMA2 path) ----------------
__device__ __forceinline__ ull packdup(float x) {
    ull d; asm("mov.b64 %0, {%1, %1};" : "=l"(d) : "f"(x)); return d;
}
__device__ __forceinline__ ull pack2(float x, float y) {
    ull d; asm("mov.b64 %0, {%1, %2};" : "=l"(d) : "f"(x), "f"(y)); return d;
}
__device__ __forceinline__ void fma2(ull &acc, ull a, ull b) {
    asm("fma.rn.f32x2 %0, %1, %2, %0;" : "+l"(acc) : "l"(a), "l"(b));
}
__device__ __forceinline__ float2 unpack2(ull v) {
    float2 r; asm("mov.b64 {%0, %1}, %2;" : "=f"(r.x), "=f"(r.y) : "l"(v)); return r;
}

// ---------------- shared tile loaders ----------------
// As: 128 rows x 16 k, padded stride 17 (conflict-free dual-broadcast reads)
__device__ __forceinline__ void load_As(float* As, const float* __restrict__ A,
                                        int row0, int Kdim, int kbase, int t) {
    int r  = t >> 1;
    int k8 = (t & 1) * 8;
    const float4* p = (const float4*)&A[(size_t)(row0 + r) * Kdim + kbase + k8];
    float4 v0 = p[0];
    float4 v1 = p[1];
    float* dst = &As[r * 17 + k8];
    dst[0] = v0.x; dst[1] = v0.y; dst[2] = v0.z; dst[3] = v0.w;
    dst[4] = v1.x; dst[5] = v1.y; dst[6] = v1.z; dst[7] = v1.w;
}

// Bs: 16 k x 128 cols, B row-major with 128 cols
__device__ __forceinline__ void load_Bs(float* Bs, const float* __restrict__ Bm,
                                        int kbase, int t) {
#pragma unroll
    for (int s = 0; s < 2; ++s) {
        int idx = t + 256 * s;          // 0..511 float4 tiles
        int kk  = idx >> 5;
        int c4  = (idx & 31) << 2;
        *(float4*)&Bs[kk * 128 + c4] =
            *(const float4*)&Bm[(size_t)(kbase + kk) * 128 + c4];
    }
}

// ---------------- 8x8 f32x2 microkernel over one 16-deep K tile ----------------
__device__ __forceinline__ void mk_compute(const float* __restrict__ As,
                                           const float* __restrict__ Bs,
                                           ull acc[8][4], int tx, int ty) {
#pragma unroll
    for (int kk = 0; kk < 16; ++kk) {
        ull ad[8];
#pragma unroll
        for (int r = 0; r < 8; ++r) ad[r] = packdup(As[(ty * 8 + r) * 17 + kk]);
        const float4 b0 = *(const float4*)&Bs[kk * 128 + tx * 8];
        const float4 b1 = *(const float4*)&Bs[kk * 128 + tx * 8 + 4];
        ull bd[4];
        bd[0] = pack2(b0.x, b0.y); bd[1] = pack2(b0.z, b0.w);
        bd[2] = pack2(b1.x, b1.y); bd[3] = pack2(b1.z, b1.w);
#pragma unroll
        for (int r = 0; r < 8; ++r)
#pragma unroll
            for (int c = 0; c < 4; ++c) fma2(acc[r][c], ad[r], bd[c]);
    }
}

// ---------------- zero scratch accumulators ----------------
__global__ void zero_kernel() {
    int i = blockIdx.x * 256 + threadIdx.x;   // 262144 each
    g_xhat[i] = 0.0f;
    g_y[i]    = 0.0f;
}

// ---------------- H tensor (transposed: Ht[j][l][k]) ----------------
__global__ void __launch_bounds__(256) ht_kernel(const float* __restrict__ Aop,
                                                 const float* __restrict__ Bop,
                                                 const float* __restrict__ Dout,
                                                 const float* __restrict__ Din,
                                                 const float* __restrict__ product) {
    int j = blockIdx.x;
    int t = threadIdx.x;
    __shared__ float Aj[NR * 64];
    __shared__ float Bj[NR * 64];
    __shared__ float Qs[64 * 64];
    for (int i = t; i < NR * 64; i += 256) {
        Aj[i] = Aop[j * (NR * 64) + i];
        Bj[i] = Bop[j * (NR * 64) + i];
    }
    __syncthreads();
#pragma unroll
    for (int s = 0; s < 16; ++s) {
        int idx = t + 256 * s;        // 4096 = 64x64
        int m = idx >> 6, n = idx & 63;
        float q = 0.0f;
#pragma unroll
        for (int r = 0; r < NR; ++r) q += Aj[r * 64 + m] * Bj[r * 64 + n];
        Qs[idx] = q;
    }
    __syncthreads();
#pragma unroll 4
    for (int s = 0; s < 64; ++s) {
        int idx = t + 256 * s;        // 16384 = 128x128
        int k = idx >> 7, l = idx & 127;
        float h = Dout[j * 128 + k] * Din[j * 128 + l] * product[k * 128 + l];
        if (k < 64 && l < 64) h += Qs[k * 64 + l];
        g_Ht[j * 16384 + l * 128 + k] = h;   // transposed (l,k)
    }
}

// ---------------- weights transpose: Wt[j][o][i] = weights[i][o][j] ----------------
__global__ void wt_kernel(const float* __restrict__ w) {
    int id = blockIdx.x * 256 + threadIdx.x;   // 262144
    int ii = id & 127;
    int o  = (id >> 7) & 127;
    int j  = id >> 14;
    g_Wt[id] = w[(ii * 128 + o) * NJ + j];
}

// ---------------- GEMM: C[2048,128] += A[2048,K] @ B[K,128], split-K + atomics ----
// MODE 0: A=x, B=wbases, C=g_xhat          (K=16384)
// MODE 1: A=g_z, B=g_Ht, C=g_y             (K=2048)
template <int MODE>
__global__ void __launch_bounds__(256) gemm_ns_kernel(const float* __restrict__ Ain,
                                                      const float* __restrict__ Bin,
                                                      int Kdim, int kchunk) {
    const float* A  = (MODE == 0) ? Ain : g_z;
    const float* Bm = (MODE == 0) ? Bin : g_Ht;
    float*       C  = (MODE == 0) ? g_xhat : g_y;

    __shared__ __align__(16) float As[128 * 17];
    __shared__ __align__(16) float Bs[16 * 128];
    int t = threadIdx.x, tx = t & 15, ty = t >> 4;
    int row0 = blockIdx.x * 128;
    int k0   = blockIdx.y * kchunk;

    ull acc[8][4];
#pragma unroll
    for (int r = 0; r < 8; ++r)
#pragma unroll
        for (int c = 0; c < 4; ++c) acc[r][c] = 0ull;

    for (int kt = 0; kt < kchunk; kt += 16) {
        load_As(As, A, row0, Kdim, k0 + kt, t);
        load_Bs(Bs, Bm, k0 + kt, t);
        __syncthreads();
        mk_compute(As, Bs, acc, tx, ty);
        __syncthreads();
    }
#pragma unroll
    for (int r = 0; r < 8; ++r) {
        int row = row0 + ty * 8 + r;
#pragma unroll
        for (int c = 0; c < 4; ++c) {
            float2 v = unpack2(acc[r][c]);
            atomicAdd(&C[row * 128 + tx * 8 + c * 2 + 0], v.x);
            atomicAdd(&C[row * 128 + tx * 8 + c * 2 + 1], v.y);
        }
    }
}

// ---------------- per-(b,j) GEMM: z[b,o,j,l] = sum_i Wt[j,o,i]*xhat[b,i,l] --------
__global__ void __launch_bounds__(256) gemm_z_kernel() {
    int bj = blockIdx.x;
    int b = bj >> 4, j = bj & 15;
    const float* A  = g_Wt  + j * 128 * 128;   // [o][i]
    const float* Bm = g_xhat + b * 128 * 128;  // [i][l]

    __shared__ __align__(16) float As[128 * 17];
    __shared__ __align__(16) float Bs[16 * 128];
    int t = threadIdx.x, tx = t & 15, ty = t >> 4;

    ull acc[8][4];
#pragma unroll
    for (int r = 0; r < 8; ++r)
#pragma unroll
        for (int c = 0; c < 4; ++c) acc[r][c] = 0ull;

    for (int kt = 0; kt < 128; kt += 16) {
        load_As(As, A, 0, 128, kt, t);
        load_Bs(Bs, Bm, kt, t);
        __syncthreads();
        mk_compute(As, Bs, acc, tx, ty);
        __syncthreads();
    }
#pragma unroll
    for (int r = 0; r < 8; ++r) {
        int o = ty * 8 + r;
#pragma unroll
        for (int c = 0; c < 4; ++c) {
            float2 v = unpack2(acc[r][c]);
            int l = tx * 8 + c * 2;
            *(float2*)&g_z[((size_t)(b * 128 + o) * NJ + j) * 128 + l] = v;
        }
    }
}

// ---------------- stage D: out[2048,16384] = Y[2048,128] @ bases^T ---------------
__global__ void __launch_bounds__(256) gemm_d_kernel(const float* __restrict__ bases,
                                                     float* __restrict__ out) {
    int row0 = blockIdx.x * 128;   // (b,o) rows
    int x0   = blockIdx.y * 128;   // npts cols

    __shared__ __align__(16) float As[128 * 17];
    __shared__ __align__(16) float Bs[16 * 128];
    int t = threadIdx.x, tx = t & 15, ty = t >> 4;

    ull acc[8][4];
#pragma unroll
    for (int r = 0; r < 8; ++r)
#pragma unroll
        for (int c = 0; c < 4; ++c) acc[r][c] = 0ull;

    for (int kt = 0; kt < 128; kt += 16) {
        load_As(As, g_y, row0, 128, kt, t);
        // transposed load of bases: Bs[kk][x] = bases[x0+x][kt+kk]
#pragma unroll
        for (int s = 0; s < 2; ++s) {
            int idx = t + 256 * s;         // 0..511
            int xr  = idx >> 2;
            int kq  = (idx & 3) << 2;
            float4 v = *(const float4*)&bases[(size_t)(x0 + xr) * 128 + kt + kq];
            Bs[(kq + 0) * 128 + xr] = v.x;
            Bs[(kq + 1) * 128 + xr] = v.y;
            Bs[(kq + 2) * 128 + xr] = v.z;
            Bs[(kq + 3) * 128 + xr] = v.w;
        }
        __syncthreads();
        mk_compute(As, Bs, acc, tx, ty);
        __syncthreads();
    }
#pragma unroll
    for (int r = 0; r < 8; ++r) {
        int row = row0 + ty * 8 + r;
#pragma unroll
        for (int c = 0; c < 4; ++c) {
            float2 v = unpack2(acc[r][c]);
            *(float2*)&out[(size_t)row * NPTS + x0 + tx * 8 + c * 2] = v;
        }
    }
}

// ---------------- launch ----------------
extern "C" void kernel_launch(void* const* d_in, const int* in_sizes, int n_in,
                              void* d_out, int out_size) {
    const float* x       = (const float*)d_in[0];
    const float* bases   = (const float*)d_in[1];
    const float* wbases  = (const float*)d_in[2];
    const float* product = (const float*)d_in[3];
    const float* Dout    = (const float*)d_in[4];
    const float* Din     = (const float*)d_in[5];
    const float* Aop     = (const float*)d_in[6];
    const float* Bop     = (const float*)d_in[7];
    const float* weights = (const float*)d_in[8];
    float* out = (float*)d_out;

    zero_kernel<<<1024, 256>>>();
    ht_kernel<<<NJ, 256>>>(Aop, Bop, Dout, Din, product);
    wt_kernel<<<1024, 256>>>(weights);
    // stage A: x_hat = X @ wbases   (K=16384, 16 splits of 1024)
    gemm_ns_kernel<0><<<dim3(16, 16), 256>>>(x, wbases, NPTS, 1024);
    // stage Z: per (b,j) mode mixing with weights
    gemm_z_kernel<<<NB * NJ, 256>>>();
    // stage Y: y = z2 @ Ht          (K=2048, 8 splits of 256)
    gemm_ns_kernel<1><<<dim3(16, 8), 256>>>(nullptr, nullptr, NJ * NL, 256);
    // stage D: out = Y @ bases^T
    gemm_d_kernel<<<dim3(16, 128), 256>>>(bases, out);
}

// round 3
// speedup vs baseline: 1.1844x; 1.1844x over previous
#include <cuda_runtime.h>

#define NB    16
#define NDIM  128
#define NPTS  16384
#define NJ    16
#define NK    128
#define NL    128
#define NR    8

typedef unsigned long long ull;

// Scratch (device globals — no allocation allowed)
__device__ float g_xhat[NB * NDIM * NL];          // [b*128+i][l]        1 MB
__device__ float g_Ht[NJ * NL * NK];              // [(j*128+l)][k]      1 MB
__device__ float g_Wt[NJ * NDIM * NDIM];          // [(j*128+o)][i]      1 MB
__device__ float g_z[NB * NDIM * NJ * NL];        // [b][o][j*128+l]    16 MB
__device__ float g_y[NB * NDIM * NK];             // [b*128+o][k]        1 MB
__device__ float g_basesT[NK * NPTS];             // [k][x]              8 MB

// ---------------- packed fp32x2 helpers ----------------
__device__ __forceinline__ ull dup2(float x) {
    ull d; asm("mov.b64 %0, {%1, %1};" : "=l"(d) : "f"(x)); return d;
}
__device__ __forceinline__ void fma2(ull &acc, ull a, ull b) {
    asm("fma.rn.f32x2 %0, %1, %2, %0;" : "+l"(acc) : "l"(a), "l"(b));
}
__device__ __forceinline__ float2 unp(ull v) {
    float2 r; asm("mov.b64 {%0, %1}, %2;" : "=f"(r.x), "=f"(r.y) : "l"(v)); return r;
}

// ---------------- double-buffered 128x128 GEMM core -----------------
// C[128,128] (+)= A[128, ktiles*8] @ B[ktiles*8, 128]
// A row-major (lda), B row-major (ldb), C row-major (ldc).
// 256 threads, 8x8 per-thread tile via fp32x2.
struct __align__(16) GemmSmem {
    ull  As[2][128 * 9];     // a values duplicated into 64-bit pairs; pad stride 9
    float Bs[2][8 * 128];
};

template <bool ATOMIC>
__device__ __forceinline__ void gemm128(const float* __restrict__ A, int lda,
                                        const float* __restrict__ B, int ldb,
                                        float* __restrict__ C, int ldc,
                                        int ktiles) {
    __shared__ GemmSmem sm;
    const int t  = threadIdx.x;
    const int tx = t & 15, ty = t >> 4;
    const int ar = t >> 1, ak4 = (t & 1) * 4;       // A tile: 128 rows x 8 k
    const int bk = t >> 5, bc4 = (t & 31) * 4;      // B tile: 8 k x 128 cols

    ull acc[8][4];
#pragma unroll
    for (int r = 0; r < 8; ++r)
#pragma unroll
        for (int c = 0; c < 4; ++c) acc[r][c] = 0ull;

    // prologue: tile 0
    {
        float4 af = *(const float4*)&A[(size_t)ar * lda + ak4];
        float4 bf = *(const float4*)&B[(size_t)bk * ldb + bc4];
#pragma unroll
        for (int i = 0; i < 4; ++i) sm.As[0][ar * 9 + ak4 + i] = dup2(((float*)&af)[i]);
        *(float4*)&sm.Bs[0][bk * 128 + bc4] = bf;
    }
    __syncthreads();

    int cur = 0;
    for (int kt = 0; kt < ktiles; ++kt) {
        float4 afn, bfn;
        const bool more = (kt + 1 < ktiles);
        if (more) {
            afn = *(const float4*)&A[(size_t)ar * lda + (kt + 1) * 8 + ak4];
            bfn = *(const float4*)&B[(size_t)(bk + (kt + 1) * 8) * ldb + bc4];
        }
#pragma unroll
        for (int kk = 0; kk < 8; ++kk) {
            ull a[8];
#pragma unroll
            for (int r = 0; r < 8; ++r) a[r] = sm.As[cur][(ty * 8 + r) * 9 + kk];
            ulonglong2 b01 = *(const ulonglong2*)&sm.Bs[cur][kk * 128 + tx * 8];
            ulonglong2 b23 = *(const ulonglong2*)&sm.Bs[cur][kk * 128 + tx * 8 + 4];
#pragma unroll
            for (int r = 0; r < 8; ++r) {
                fma2(acc[r][0], a[r], b01.x);
                fma2(acc[r][1], a[r], b01.y);
                fma2(acc[r][2], a[r], b23.x);
                fma2(acc[r][3], a[r], b23.y);
            }
        }
        if (more) {
            const int nxt = cur ^ 1;
#pragma unroll
            for (int i = 0; i < 4; ++i) sm.As[nxt][ar * 9 + ak4 + i] = dup2(((float*)&afn)[i]);
            *(float4*)&sm.Bs[nxt][bk * 128 + bc4] = bfn;
            __syncthreads();
            cur = nxt;
        }
    }

#pragma unroll
    for (int r = 0; r < 8; ++r) {
        const int row = ty * 8 + r;
#pragma unroll
        for (int c = 0; c < 4; ++c) {
            float2 v = unp(acc[r][c]);
            const int col = tx * 8 + c * 2;
            if (ATOMIC) {
                atomicAdd(&C[(size_t)row * ldc + col + 0], v.x);
                atomicAdd(&C[(size_t)row * ldc + col + 1], v.y);
            } else {
                *(float2*)&C[(size_t)row * ldc + col] = v;
            }
        }
    }
}

// ---------------- prep kernels ----------------
__global__ void zero_kernel() {
    int i = blockIdx.x * 256 + threadIdx.x;   // 262144 each
    g_xhat[i] = 0.0f;
    g_y[i]    = 0.0f;
}

__global__ void __launch_bounds__(256) ht_kernel(const float* __restrict__ Aop,
                                                 const float* __restrict__ Bop,
                                                 const float* __restrict__ Dout,
                                                 const float* __restrict__ Din,
                                                 const float* __restrict__ product) {
    int j = blockIdx.x;
    int t = threadIdx.x;
    __shared__ float Aj[NR * 64];
    __shared__ float Bj[NR * 64];
    __shared__ float Qs[64 * 64];
    for (int i = t; i < NR * 64; i += 256) {
        Aj[i] = Aop[j * (NR * 64) + i];
        Bj[i] = Bop[j * (NR * 64) + i];
    }
    __syncthreads();
#pragma unroll
    for (int s = 0; s < 16; ++s) {
        int idx = t + 256 * s;        // 4096 = 64x64
        int m = idx >> 6, n = idx & 63;
        float q = 0.0f;
#pragma unroll
        for (int r = 0; r < NR; ++r) q += Aj[r * 64 + m] * Bj[r * 64 + n];
        Qs[idx] = q;
    }
    __syncthreads();
#pragma unroll 4
    for (int s = 0; s < 64; ++s) {
        int idx = t + 256 * s;        // 16384 = 128x128
        int k = idx >> 7, l = idx & 127;
        float h = Dout[j * 128 + k] * Din[j * 128 + l] * product[k * 128 + l];
        if (k < 64 && l < 64) h += Qs[k * 64 + l];
        g_Ht[j * 16384 + l * 128 + k] = h;   // transposed (l,k)
    }
}

__global__ void wt_kernel(const float* __restrict__ w) {
    int id = blockIdx.x * 256 + threadIdx.x;   // 262144
    int ii = id & 127;
    int o  = (id >> 7) & 127;
    int j  = id >> 14;
    g_Wt[id] = w[(ii * 128 + o) * NJ + j];
}

// bases[NPTS][128] -> g_basesT[128][NPTS]
__global__ void __launch_bounds__(256) transpose_kernel(const float* __restrict__ bases) {
    __shared__ float tile[32][33];
    int xb = blockIdx.x * 32, kb = blockIdx.y * 32;
    int tx = threadIdx.x & 31, tyy = threadIdx.x >> 5;  // 8 rows of 32
#pragma unroll
    for (int i = 0; i < 32; i += 8)
        tile[tyy + i][tx] = bases[(size_t)(xb + tyy + i) * 128 + kb + tx];
    __syncthreads();
#pragma unroll
    for (int i = 0; i < 32; i += 8)
        g_basesT[(size_t)(kb + tyy + i) * NPTS + xb + tx] = tile[tx][tyy + i];
}

// ---------------- GEMM stage kernels ----------------
// stage A: g_xhat[2048,128] += x[2048,16384] @ wbases[16384,128] (split-K)
__global__ void __launch_bounds__(256) k_gemm_a(const float* __restrict__ x,
                                                const float* __restrict__ wb,
                                                int split_tiles) {
    const int row0 = blockIdx.x * 128;
    const int kt0  = blockIdx.y * split_tiles;
    const int ktiles = min(split_tiles, 2048 - kt0);   // 16384/8 total tiles
    if (ktiles <= 0) return;
    gemm128<true>(x + (size_t)row0 * NPTS + (size_t)kt0 * 8, NPTS,
                  wb + (size_t)kt0 * 8 * 128, 128,
                  g_xhat + (size_t)row0 * 128, 128, ktiles);
}

// stage Z: per (b,j): z[b,:,j,:] = Wt[j] @ xhat[b]   (K=128)
__global__ void __launch_bounds__(256) k_gemm_z() {
    const int b = blockIdx.x >> 4, j = blockIdx.x & 15;
    gemm128<false>(g_Wt + (size_t)j * 128 * 128, 128,
                   g_xhat + (size_t)b * 128 * 128, 128,
                   g_z + ((size_t)(b * 128) * NJ + j) * 128, NJ * 128, 16);
}

// stage Y: g_y[2048,128] += z2[2048,2048] @ Ht[2048,128] (split-K)
__global__ void __launch_bounds__(256) k_gemm_y(int split_tiles) {
    const int row0 = blockIdx.x * 128;
    const int kt0  = blockIdx.y * split_tiles;
    const int ktiles = min(split_tiles, 256 - kt0);    // 2048/8 total tiles
    if (ktiles <= 0) return;
    gemm128<true>(g_z + (size_t)row0 * 2048 + (size_t)kt0 * 8, 2048,
                  g_Ht + (size_t)kt0 * 8 * 128, 128,
                  g_y + (size_t)row0 * 128, 128, ktiles);
}

// stage D: out[2048,16384] = g_y[2048,128] @ g_basesT[128,16384]
__global__ void __launch_bounds__(256) k_gemm_d(float* __restrict__ out) {
    const int row0 = blockIdx.x * 128;
    const int x0   = blockIdx.y * 128;
    gemm128<false>(g_y + (size_t)row0 * 128, 128,
                   g_basesT + x0, NPTS,
                   out + (size_t)row0 * NPTS + x0, NPTS, 16);
}

// ---------------- launch ----------------
extern "C" void kernel_launch(void* const* d_in, const int* in_sizes, int n_in,
                              void* d_out, int out_size) {
    const float* x       = (const float*)d_in[0];
    const float* bases   = (const float*)d_in[1];
    const float* wbases  = (const float*)d_in[2];
    const float* product = (const float*)d_in[3];
    const float* Dout    = (const float*)d_in[4];
    const float* Din     = (const float*)d_in[5];
    const float* Aop     = (const float*)d_in[6];
    const float* Bop     = (const float*)d_in[7];
    const float* weights = (const float*)d_in[8];
    float* out = (float*)d_out;

    zero_kernel<<<1024, 256>>>();
    ht_kernel<<<NJ, 256>>>(Aop, Bop, Dout, Din, product);
    wt_kernel<<<1024, 256>>>(weights);
    transpose_kernel<<<dim3(NPTS / 32, 4), 256>>>(bases);

    // stage A: 16 row-blocks x 9 K-splits = 144 CTAs (~1 wave), 228 tiles/split
    k_gemm_a<<<dim3(16, 9), 256>>>(x, wbases, 228);
    // stage Z: 256 CTAs
    k_gemm_z<<<NB * NJ, 256>>>();
    // stage Y: 16 x 9 = 144 CTAs, 29 tiles/split
    k_gemm_y<<<dim3(16, 9), 256>>>(29);
    // stage D: 16 x 128 = 2048 CTAs
    k_gemm_d<<<dim3(16, 128), 256>>>(out);
}

// round 5
// speedup vs baseline: 3.3992x; 2.8699x over previous
#include <cuda_runtime.h>
#include <cuda_bf16.h>
#include <cstdint>

#define NB    16
#define NDIM  128
#define NPTS  16384
#define NJ    16
#define NR    8
#define KT    32                     // K-tile depth
#define ROWPAD 40                    // padded smem row (elements)
#define TILE_B (128 * ROWPAD * 2)    // 10240 bytes per bf16 tile
#define BUF_B  (4 * TILE_B)          // Ah|Al|Bh|Bl = 40960
#define SMEM_B (2 * BUF_B)           // double buffer = 81920

// ---------------- device scratch ----------------
__device__ float g_xhat [NB * NDIM * 128];      // [(b,i)][l]      1 MB
__device__ float g_xhatT[NB * 128 * NDIM];      // [b][l][i]       1 MB
__device__ float g_Wt   [NJ * NDIM * NDIM];     // [j][o][i]       1 MB
__device__ float g_Hk   [128 * NJ * 128];       // [k][(j,l)]      1 MB
__device__ float g_z    [NB * NDIM * NJ * 128]; // [(b,o)][(j,l)] 16 MB
__device__ float g_y    [NB * NDIM * 128];      // [(b,o)][k]      1 MB
__device__ float g_wbT  [128 * NPTS];           // [l][x]          8 MB

// ---------------- helpers ----------------
__device__ __forceinline__ uint32_t smem_u32(const void* p) {
    uint32_t a;
    asm("{ .reg .u64 t; cvta.to.shared.u64 t, %1; cvt.u32.u64 %0, t; }" : "=r"(a) : "l"(p));
    return a;
}
__device__ __forceinline__ void ldmx4(uint32_t* r, uint32_t addr) {
    asm volatile("ldmatrix.sync.aligned.m8n8.x4.shared.b16 {%0,%1,%2,%3}, [%4];"
                 : "=r"(r[0]), "=r"(r[1]), "=r"(r[2]), "=r"(r[3]) : "r"(addr));
}
__device__ __forceinline__ void mma_bf16(float* c, const uint32_t* a, const uint32_t* b) {
    asm volatile("mma.sync.aligned.m16n8k16.row.col.f32.bf16.bf16.f32 "
                 "{%0,%1,%2,%3}, {%4,%5,%6,%7}, {%8,%9}, {%0,%1,%2,%3};"
                 : "+f"(c[0]), "+f"(c[1]), "+f"(c[2]), "+f"(c[3])
                 : "r"(a[0]), "r"(a[1]), "r"(a[2]), "r"(a[3]), "r"(b[0]), "r"(b[1]));
}
// fp32x4 -> bf16 hi pair + lo (residual) pair
__device__ __forceinline__ void cvt_hl(float4 v, uint2& hi, uint2& lo) {
    __nv_bfloat162 h0 = __floats2bfloat162_rn(v.x, v.y);
    __nv_bfloat162 h1 = __floats2bfloat162_rn(v.z, v.w);
    uint32_t u0 = *(uint32_t*)&h0, u1 = *(uint32_t*)&h1;
    float rx = v.x - __uint_as_float(u0 << 16);
    float ry = v.y - __uint_as_float(u0 & 0xffff0000u);
    float rz = v.z - __uint_as_float(u1 << 16);
    float rw = v.w - __uint_as_float(u1 & 0xffff0000u);
    __nv_bfloat162 l0 = __floats2bfloat162_rn(rx, ry);
    __nv_bfloat162 l1 = __floats2bfloat162_rn(rz, rw);
    hi = make_uint2(u0, u1);
    lo = make_uint2(*(uint32_t*)&l0, *(uint32_t*)&l1);
}

// ---------------- HMMA 128x128 GEMM core ----------------
// C[128,128] (+)= A[128, ktiles*32] @ Bt[128, ktiles*32]^T
// A, Bt fp32 K-major row-major. bf16 hi/lo 3-term emulation on tensor pipe.
template <bool ATOMIC>
__device__ __forceinline__ void mm_core(const float* __restrict__ A, int lda,
                                        const float* __restrict__ B, int ldb,
                                        float* __restrict__ C, int ldc, int ktiles) {
    extern __shared__ __align__(128) char dsm[];
    const int t = threadIdx.x, lane = t & 31, w = t >> 5;
    const int wr = w >> 2, wc = w & 3;            // warp grid 2 x 4 (64x32 tiles)
    const uint32_t sb = smem_u32(dsm);

    // ldmatrix per-lane byte offsets (row stride 80B)
    const int a_off = ((lane & 7) + ((lane >> 3) & 1) * 8) * 80 + ((lane >> 4) & 1) * 16;
    const int b_off = ((lane & 7) + ((lane >> 4) & 1) * 8) * 80 + ((lane >> 3) & 1) * 16;

    float acc[16][4];
#pragma unroll
    for (int i = 0; i < 16; ++i)
#pragma unroll
        for (int j = 0; j < 4; ++j) acc[i][j] = 0.0f;

    float4 av[4], bv[4];

    // ---- prologue: tile 0 ----
#pragma unroll
    for (int i = 0; i < 4; ++i) {
        const int idx = t + 256 * i, r = idx >> 3, c4 = (idx & 7) << 2;
        av[i] = *(const float4*)&A[(size_t)r * lda + c4];
        bv[i] = *(const float4*)&B[(size_t)r * ldb + c4];
    }
#pragma unroll
    for (int i = 0; i < 4; ++i) {
        const int idx = t + 256 * i, r = idx >> 3, c4 = (idx & 7) << 2;
        const uint32_t eo = r * 80 + c4 * 2;
        uint2 hi, lo;
        cvt_hl(av[i], hi, lo);
        *(uint2*)(dsm + 0 * TILE_B + eo) = hi;
        *(uint2*)(dsm + 1 * TILE_B + eo) = lo;
        cvt_hl(bv[i], hi, lo);
        *(uint2*)(dsm + 2 * TILE_B + eo) = hi;
        *(uint2*)(dsm + 3 * TILE_B + eo) = lo;
    }
    __syncthreads();

    int cur = 0;
    for (int kt = 0; kt < ktiles; ++kt) {
        const bool more = (kt + 1 < ktiles);
        if (more) {
#pragma unroll
            for (int i = 0; i < 4; ++i) {
                const int idx = t + 256 * i, r = idx >> 3, c4 = (idx & 7) << 2;
                av[i] = *(const float4*)&A[(size_t)r * lda + (kt + 1) * KT + c4];
                bv[i] = *(const float4*)&B[(size_t)r * ldb + (kt + 1) * KT + c4];
            }
        }

        // ---- compute on buffer cur ----
        const uint32_t bb = sb + cur * BUF_B;
#pragma unroll
        for (int ks = 0; ks < 2; ++ks) {
            const uint32_t koff = ks * 32;        // 16 elements * 2B
            uint32_t bh[4][2], bl[4][2];
#pragma unroll
            for (int n2 = 0; n2 < 2; ++n2) {
                const uint32_t nbase = (wc * 32 + n2 * 16) * 80 + koff + b_off;
                uint32_t r4[4];
                ldmx4(r4, bb + 2 * TILE_B + nbase);
                bh[n2 * 2][0] = r4[0]; bh[n2 * 2][1] = r4[1];
                bh[n2 * 2 + 1][0] = r4[2]; bh[n2 * 2 + 1][1] = r4[3];
                ldmx4(r4, bb + 3 * TILE_B + nbase);
                bl[n2 * 2][0] = r4[0]; bl[n2 * 2][1] = r4[1];
                bl[n2 * 2 + 1][0] = r4[2]; bl[n2 * 2 + 1][1] = r4[3];
            }
#pragma unroll
            for (int mi = 0; mi < 4; ++mi) {
                const uint32_t mbase = (wr * 64 + mi * 16) * 80 + koff + a_off;
                uint32_t ah[4], al[4];
                ldmx4(ah, bb + 0 * TILE_B + mbase);
                ldmx4(al, bb + 1 * TILE_B + mbase);
#pragma unroll
                for (int ni = 0; ni < 4; ++ni) {
                    mma_bf16(acc[mi * 4 + ni], ah, bh[ni]);
                    mma_bf16(acc[mi * 4 + ni], ah, bl[ni]);
                    mma_bf16(acc[mi * 4 + ni], al, bh[ni]);
                }
            }
        }

        if (more) {
            const int nxt = cur ^ 1;
#pragma unroll
            for (int i = 0; i < 4; ++i) {
                const int idx = t + 256 * i, r = idx >> 3, c4 = (idx & 7) << 2;
                const uint32_t eo = nxt * BUF_B + r * 80 + c4 * 2;
                uint2 hi, lo;
                cvt_hl(av[i], hi, lo);
                *(uint2*)(dsm + eo + 0 * TILE_B) = hi;
                *(uint2*)(dsm + eo + 1 * TILE_B) = lo;
                cvt_hl(bv[i], hi, lo);
                *(uint2*)(dsm + eo + 2 * TILE_B) = hi;
                *(uint2*)(dsm + eo + 3 * TILE_B) = lo;
            }
            __syncthreads();
            cur = nxt;
        }
    }

    // ---- epilogue ----
#pragma unroll
    for (int mi = 0; mi < 4; ++mi)
#pragma unroll
        for (int ni = 0; ni < 4; ++ni) {
            const int row = wr * 64 + mi * 16 + (lane >> 2);
            const int col = wc * 32 + ni * 8 + (lane & 3) * 2;
            const float* a = acc[mi * 4 + ni];
            if (ATOMIC) {
                atomicAdd(&C[(size_t)row * ldc + col],           a[0]);
                atomicAdd(&C[(size_t)row * ldc + col + 1],       a[1]);
                atomicAdd(&C[(size_t)(row + 8) * ldc + col],     a[2]);
                atomicAdd(&C[(size_t)(row + 8) * ldc + col + 1], a[3]);
            } else {
                *(float2*)&C[(size_t)row * ldc + col]       = make_float2(a[0], a[1]);
                *(float2*)&C[(size_t)(row + 8) * ldc + col] = make_float2(a[2], a[3]);
            }
        }
}

// ---------------- prep kernels ----------------
__global__ void zero_kernel() {
    int i = blockIdx.x * 256 + threadIdx.x;   // 262144 each
    g_xhat[i] = 0.0f;
    g_y[i]    = 0.0f;
}

__global__ void __launch_bounds__(256) ht_kernel(const float* __restrict__ Aop,
                                                 const float* __restrict__ Bop,
                                                 const float* __restrict__ Dout,
                                                 const float* __restrict__ Din,
                                                 const float* __restrict__ product) {
    int j = blockIdx.x;
    int t = threadIdx.x;
    __shared__ float Aj[NR * 64];
    __shared__ float Bj[NR * 64];
    __shared__ float Qs[64 * 64];
    for (int i = t; i < NR * 64; i += 256) {
        Aj[i] = Aop[j * (NR * 64) + i];
        Bj[i] = Bop[j * (NR * 64) + i];
    }
    __syncthreads();
#pragma unroll
    for (int s = 0; s < 16; ++s) {
        int idx = t + 256 * s;
        int m = idx >> 6, n = idx & 63;
        float q = 0.0f;
#pragma unroll
        for (int r = 0; r < NR; ++r) q += Aj[r * 64 + m] * Bj[r * 64 + n];
        Qs[idx] = q;
    }
    __syncthreads();
#pragma unroll 4
    for (int s = 0; s < 64; ++s) {
        int idx = t + 256 * s;        // 16384 = 128x128
        int k = idx >> 7, l = idx & 127;
        float h = Dout[j * 128 + k] * Din[j * 128 + l] * product[k * 128 + l];
        if (k < 64 && l < 64) h += Qs[k * 64 + l];
        g_Hk[k * (NJ * 128) + j * 128 + l] = h;   // [k][(j,l)]
    }
}

__global__ void wt_kernel(const float* __restrict__ w) {
    int id = blockIdx.x * 256 + threadIdx.x;   // 262144
    int ii = id & 127;
    int o  = (id >> 7) & 127;
    int j  = id >> 14;
    g_Wt[id] = w[(ii * 128 + o) * NJ + j];
}

// wbases[NPTS][128] -> g_wbT[128][NPTS]
__global__ void __launch_bounds__(256) twb_kernel(const float* __restrict__ wb) {
    __shared__ float tile[32][33];
    int xb = blockIdx.x * 32, kb = blockIdx.y * 32;
    int tx = threadIdx.x & 31, ty = threadIdx.x >> 5;
#pragma unroll
    for (int i = 0; i < 32; i += 8)
        tile[ty + i][tx] = wb[(size_t)(xb + ty + i) * 128 + kb + tx];
    __syncthreads();
#pragma unroll
    for (int i = 0; i < 32; i += 8)
        g_wbT[(size_t)(kb + ty + i) * NPTS + xb + tx] = tile[tx][ty + i];
}

// g_xhat[b][i][l] -> g_xhatT[b][l][i]
__global__ void __launch_bounds__(256) txh_kernel() {
    __shared__ float tile[32][33];
    int b = blockIdx.z;
    int ib = blockIdx.x * 32, lb = blockIdx.y * 32;
    int tx = threadIdx.x & 31, ty = threadIdx.x >> 5;
    const float* src = g_xhat + (size_t)b * 128 * 128;
    float* dst = g_xhatT + (size_t)b * 128 * 128;
#pragma unroll
    for (int i = 0; i < 32; i += 8)
        tile[ty + i][tx] = src[(ib + ty + i) * 128 + lb + tx];
    __syncthreads();
#pragma unroll
    for (int i = 0; i < 32; i += 8)
        dst[(lb + ty + i) * 128 + ib + tx] = tile[tx][ty + i];
}

// ---------------- GEMM stage kernels ----------------
// stage A: xhat[2048,128] += x[2048,16384] @ wbases  (512 ktiles, 9 splits)
__global__ void __launch_bounds__(256) k_mm_a(const float* __restrict__ x) {
    const int row0 = blockIdx.x * 128;
    const int kt0  = blockIdx.y * 57;
    const int kt   = min(57, 512 - kt0);
    if (kt <= 0) return;
    mm_core<true>(x + (size_t)row0 * NPTS + kt0 * KT, NPTS,
                  g_wbT + kt0 * KT, NPTS,
                  g_xhat + (size_t)row0 * 128, 128, kt);
}

// stage Z: z[b,:, (j,:)] = Wt[j] @ xhatT[b]^T   (K=128 -> 4 ktiles)
__global__ void __launch_bounds__(256) k_mm_z() {
    const int b = blockIdx.x >> 4, j = blockIdx.x & 15;
    mm_core<false>(g_Wt + (size_t)j * 16384, 128,
                   g_xhatT + (size_t)b * 16384, 128,
                   g_z + (size_t)b * 128 * 2048 + j * 128, 2048, 4);
}

// stage Y: y[2048,128] += z[2048,2048] @ H   (64 ktiles, 8 splits)
__global__ void __launch_bounds__(256) k_mm_y() {
    const int row0 = blockIdx.x * 128;
    const int kt0  = blockIdx.y * 8;
    mm_core<true>(g_z + (size_t)row0 * 2048 + kt0 * KT, 2048,
                  g_Hk + kt0 * KT, 2048,
                  g_y + (size_t)row0 * 128, 128, 8);
}

// stage D: out[2048,16384] = y[2048,128] @ bases^T   (K=128 -> 4 ktiles)
__global__ void __launch_bounds__(256) k_mm_d(const float* __restrict__ bases,
                                              float* __restrict__ out) {
    const int row0 = blockIdx.x * 128;
    const int x0   = blockIdx.y * 128;
    mm_core<false>(g_y + (size_t)row0 * 128, 128,
                   bases + (size_t)x0 * 128, 128,
                   out + (size_t)row0 * NPTS + x0, NPTS, 4);
}

// ---------------- launch ----------------
extern "C" void kernel_launch(void* const* d_in, const int* in_sizes, int n_in,
                              void* d_out, int out_size) {
    const float* x       = (const float*)d_in[0];
    const float* bases   = (const float*)d_in[1];
    const float* wbases  = (const float*)d_in[2];
    const float* product = (const float*)d_in[3];
    const float* Dout    = (const float*)d_in[4];
    const float* Din     = (const float*)d_in[5];
    const float* Aop     = (const float*)d_in[6];
    const float* Bop     = (const float*)d_in[7];
    const float* weights = (const float*)d_in[8];
    float* out = (float*)d_out;

    cudaFuncSetAttribute(k_mm_a, cudaFuncAttributeMaxDynamicSharedMemorySize, SMEM_B);
    cudaFuncSetAttribute(k_mm_z, cudaFuncAttributeMaxDynamicSharedMemorySize, SMEM_B);
    cudaFuncSetAttribute(k_mm_y, cudaFuncAttributeMaxDynamicSharedMemorySize, SMEM_B);
    cudaFuncSetAttribute(k_mm_d, cudaFuncAttributeMaxDynamicSharedMemorySize, SMEM_B);

    zero_kernel<<<1024, 256>>>();
    ht_kernel<<<NJ, 256>>>(Aop, Bop, Dout, Din, product);
    wt_kernel<<<1024, 256>>>(weights);
    twb_kernel<<<dim3(NPTS / 32, 4), 256>>>(wbases);

    k_mm_a<<<dim3(16, 9), 256, SMEM_B>>>(x);
    txh_kernel<<<dim3(4, 4, NB), 256>>>();
    k_mm_z<<<NB * NJ, 256, SMEM_B>>>();
    k_mm_y<<<dim3(16, 8), 256, SMEM_B>>>();
    k_mm_d<<<dim3(16, 128), 256, SMEM_B>>>(bases, out);
}